// round 1
// baseline (speedup 1.0000x reference)
#include <cuda_runtime.h>
#include <math.h>

// Problem constants (fixed by the dataset)
#define BB   256   // batch
#define TT   512   // time steps
#define HH   512   // hidden
#define II   256   // input dim
#define N4H  2048  // 4*H gate columns

// Tiling
#define BT   32    // batch tile per CTA
#define HT   32    // h tile per CTA
#define KC   32    // K chunk
#define NCTA 128   // (256/32) * (512/32) = 8 * 16
#define NTHR 256   // 8 warps

// Inter-step double-buffered hidden state + grid barrier state
__device__ float g_hbuf[2][BB * HH];
__device__ unsigned int g_arr;
__device__ unsigned int g_gen;

// ---- packed f32x2 helpers (Blackwell) ----
__device__ __forceinline__ unsigned long long pk2(float a, float b) {
    unsigned long long r;
    asm("mov.b64 %0, {%1,%2};" : "=l"(r) : "f"(a), "f"(b));
    return r;
}
__device__ __forceinline__ void upk2(unsigned long long v, float &a, float &b) {
    asm("mov.b64 {%0,%1}, %2;" : "=f"(a), "=f"(b) : "l"(v));
}
__device__ __forceinline__ void fma2(unsigned long long &d, unsigned long long a,
                                     unsigned long long b) {
    asm("fma.rn.f32x2 %0, %1, %2, %0;" : "+l"(d) : "l"(a), "l"(b));
}
__device__ __forceinline__ float sigmf_(float x) { return 1.0f / (1.0f + expf(-x)); }

// ---- software grid barrier (sense via generation counter) ----
__device__ __forceinline__ void gridbar() {
    __syncthreads();
    if (threadIdx.x == 0) {
        unsigned int gen = *((volatile unsigned int *)&g_gen);
        __threadfence();
        if (atomicAdd(&g_arr, 1u) == (unsigned int)(NCTA - 1)) {
            g_arr = 0u;
            __threadfence();
            *((volatile unsigned int *)&g_gen) = gen + 1u;
        } else {
            while (*((volatile unsigned int *)&g_gen) == gen) { __nanosleep(64); }
        }
    }
    __syncthreads();
    __threadfence();  // acquire: make other CTAs' h writes visible
}

struct SMem {
    float  h[KC][BT + 1];   // +1 pad: conflict-free strided store / row read
    float4 u4[KC][32];      // [k][g*8 + hl4] : col layout g*32 + hl (floats)
};

// acc[2g+jp] accumulates gate g for h-pair (hl = w*4+2jp, +1), b = b0+lane.
template <bool CG>
__device__ __forceinline__ void gemm_acc(
    unsigned long long acc[8],
    const float *__restrict__ src, int lds,      // src[b*lds + k]
    const float *__restrict__ Wm,                // Wm[k*2048 + n]
    int K, int b0, int h0i, int tid, int lane, int w,
    bool xc, float tau, SMem *sm)
{
    const int bl = tid >> 3;          // 0..31 batch row (local)
    const int kb = (tid & 7) << 2;    // 0,4,...,28 k offset
    const float *hp = src + (size_t)(b0 + bl) * lds + kb;

    float4 hreg;
    float4 ureg[4];

    // preload chunk 0
    hreg = CG ? __ldcg((const float4 *)hp) : *(const float4 *)hp;
    if (xc && kb == 0) {  // on-the-fly xcorr on h[:,0:2] (this float4 holds k=0..3)
        float a = hreg.x, b = hreg.y;
        hreg.x = a + tau * (1.5f * a + b * (1.0f / 1.5f));
        hreg.y = b + tau * (-1.5f * a);
    }
#pragma unroll
    for (int r = 0; r < 4; ++r) {
        int idx = tid + NTHR * r;
        int kc = idx >> 5, c4 = idx & 31;
        ureg[r] = *(const float4 *)(Wm + (size_t)kc * N4H + ((c4 >> 3) << 9) + h0i +
                                    ((c4 & 7) << 2));
    }

    for (int k0 = 0; k0 < K; k0 += KC) {
        __syncthreads();
        sm->h[kb + 0][bl] = hreg.x;
        sm->h[kb + 1][bl] = hreg.y;
        sm->h[kb + 2][bl] = hreg.z;
        sm->h[kb + 3][bl] = hreg.w;
#pragma unroll
        for (int r = 0; r < 4; ++r) {
            int idx = tid + NTHR * r;
            sm->u4[idx >> 5][idx & 31] = ureg[r];
        }
        __syncthreads();

        const int kn = k0 + KC;
        if (kn < K) {  // prefetch next chunk while computing
            const float *hp2 = hp + kn;
            hreg = CG ? __ldcg((const float4 *)hp2) : *(const float4 *)hp2;
#pragma unroll
            for (int r = 0; r < 4; ++r) {
                int idx = tid + NTHR * r;
                int kc = idx >> 5, c4 = idx & 31;
                ureg[r] = *(const float4 *)(Wm + (size_t)(kn + kc) * N4H +
                                            ((c4 >> 3) << 9) + h0i + ((c4 & 7) << 2));
            }
        }

        const float *uf = (const float *)sm->u4;
        const float *hf = &sm->h[0][0];
#pragma unroll 8
        for (int k = 0; k < KC; ++k) {
            float hv = hf[k * (BT + 1) + lane];
            unsigned long long hh = pk2(hv, hv);
            const unsigned long long *row =
                (const unsigned long long *)(uf + k * 128 + (w << 2));
            fma2(acc[0], row[0],  hh);   // gate 0, h pair 0
            fma2(acc[1], row[1],  hh);   // gate 0, h pair 1
            fma2(acc[2], row[16], hh);   // gate 1
            fma2(acc[3], row[17], hh);
            fma2(acc[4], row[32], hh);   // gate 2
            fma2(acc[5], row[33], hh);
            fma2(acc[6], row[48], hh);   // gate 3
            fma2(acc[7], row[49], hh);
        }
    }
}

__global__ void __launch_bounds__(NTHR, 1) lstm_persist(
    const float *__restrict__ rnn, const int *__restrict__ bsz,
    const float *__restrict__ h0in, const float *__restrict__ c0in,
    const float *__restrict__ taup, const float *__restrict__ Ww,
    const float *__restrict__ Wb, const float *__restrict__ Uw,
    float *__restrict__ out)
{
    __shared__ SMem sm;
    const int tid  = threadIdx.x;
    const int lane = tid & 31;
    const int w    = tid >> 5;
    const int cta  = blockIdx.x;
    const int b0   = (cta & 7) * BT;    // 8 batch tiles
    const int h0i  = (cta >> 3) * HT;   // 16 h tiles
    const float tau = *taup;
    const int hbase = h0i + (w << 2);   // this thread's 4 h indices
    const int b = b0 + lane;            // this thread's batch row

    // ---- pre = x0 @ W_w + W_b (kept in registers, time-invariant) ----
    unsigned long long pre[8];
#pragma unroll
    for (int i = 0; i < 8; ++i) pre[i] = 0ull;
    gemm_acc<false>(pre, rnn, II, Ww, II, b0, h0i, tid, lane, w, false, 0.0f, &sm);
#pragma unroll
    for (int g = 0; g < 4; ++g) {
#pragma unroll
        for (int jp = 0; jp < 2; ++jp) {
            float a, c;
            upk2(pre[g * 2 + jp], a, c);
            int col = (g << 9) + hbase + (jp << 1);
            pre[g * 2 + jp] = pk2(a + Wb[col], c + Wb[col + 1]);
        }
    }

    // ---- c lives in registers for all 512 steps ----
    float creg[4], hlast[4];
#pragma unroll
    for (int j = 0; j < 4; ++j) creg[j] = c0in[(size_t)b * HH + hbase + j];
#pragma unroll
    for (int j = 0; j < 4; ++j) hlast[j] = 0.0f;

    for (int t = 0; t < TT; ++t) {
        const float *hsrc = (t == 0) ? h0in : g_hbuf[(t + 1) & 1];
        float *hdst = g_hbuf[t & 1];

        unsigned long long acc[8];
#pragma unroll
        for (int i = 0; i < 8; ++i) acc[i] = pre[i];
        gemm_acc<true>(acc, hsrc, HH, Uw, HH, b0, h0i, tid, lane, w, (t > 0), tau, &sm);

        const int bs = bsz[t];
        const bool act = (b < bs);

        float gv[4][4];  // [gate][j]
#pragma unroll
        for (int g = 0; g < 4; ++g) {
            upk2(acc[g * 2 + 0], gv[g][0], gv[g][1]);
            upk2(acc[g * 2 + 1], gv[g][2], gv[g][3]);
        }

        const float *hrow = hsrc + (size_t)b * HH;
        float *orow = out + (size_t)t * BB * HH + (size_t)b * HH;
        float *drow = hdst + (size_t)b * HH;
#pragma unroll
        for (int j = 0; j < 4; ++j) {
            float cn = sigmf_(gv[1][j]) * creg[j] + sigmf_(gv[0][j]) * tanhf(gv[2][j]);
            float hn = sigmf_(gv[3][j]) * tanhf(cn);
            float hw, ow;
            if (act) {
                creg[j] = cn;
                hw = hn;
                ow = hn;
            } else {
                int hj = hbase + j;
                float old = __ldcg(hrow + hj);
                if (t > 0 && hj < 2) {  // inactive rows still drift on dims 0,1
                    float a0 = __ldcg(hrow + 0), a1 = __ldcg(hrow + 1);
                    old = (hj == 0) ? (a0 + tau * (1.5f * a0 + a1 * (1.0f / 1.5f)))
                                    : (a1 + tau * (-1.5f * a0));
                }
                hw = old;
                ow = 0.0f;
            }
            hlast[j] = hw;
            __stcg(drow + hbase + j, hw);
            orow[hbase + j] = ow;
        }
        gridbar();
    }

    // ---- final h, c appended after outputs ----
    const size_t ofs = (size_t)TT * BB * HH;
#pragma unroll
    for (int j = 0; j < 4; ++j) {
        out[ofs + (size_t)b * HH + hbase + j] = hlast[j];
        out[ofs + (size_t)BB * HH + (size_t)b * HH + hbase + j] = creg[j];
    }
}

extern "C" void kernel_launch(void *const *d_in, const int *in_sizes, int n_in,
                              void *d_out, int out_size)
{
    const float *rnn  = (const float *)d_in[0];  // (B*T, I) fp32 — only first B rows used
    const int   *bsz  = (const int *)d_in[1];    // (T,) int32
    const float *h0   = (const float *)d_in[2];  // (1,B,H)
    const float *c0   = (const float *)d_in[3];  // (1,B,H)
    const float *tau  = (const float *)d_in[4];  // scalar
    const float *Ww   = (const float *)d_in[5];  // (I,4H)
    const float *Wb   = (const float *)d_in[6];  // (4H,)
    const float *Uw   = (const float *)d_in[7];  // (H,4H)
    float *out = (float *)d_out;                 // T*B*H outputs, then h, then c

    lstm_persist<<<NCTA, NTHR>>>(rnn, bsz, h0, c0, tau, Ww, Wb, Uw, out);
}